// round 2
// baseline (speedup 1.0000x reference)
#include <cuda_runtime.h>

#define NROWS 1024
#define DIM   256
#define HID   512

// Scratch (no allocations allowed) -------------------------------------------
__device__ __align__(16) float  g_A1 [NROWS * HID];   // relu(H@W1+b1)
__device__ __align__(16) float  g_A1g[NROWS * HID];   // relu([H,P]@W1g+b1g)
__device__ __align__(16) float  g_ymean[2 * DIM];     // col means: pathways | global_embed
__device__ double g_acc;                              // final accumulator

// ----------------------------------------------------------------------------
// Column means of the two [N, DIM] "y" tensors (double accumulation) + zero acc
__global__ void init_kernel(const float* __restrict__ P, const float* __restrict__ G)
{
    const float* Y = (blockIdx.x == 0) ? P : G;
    int d = threadIdx.x;                 // 256 threads = 256 columns, coalesced rows
    double s = 0.0;
    for (int j = 0; j < NROWS; ++j) s += (double)Y[j * DIM + d];
    g_ymean[blockIdx.x * DIM + d] = (float)(s * (1.0 / NROWS));
    if (blockIdx.x == 0 && d == 0) g_acc = 0.0;
}

// ----------------------------------------------------------------------------
// Tiled fp32 GEMM.  Out[m,n] = sum_k Xcat[m,k] * W[k,n]  (+bias, then epilogue)
//   Xcat[m,k] = (k < Kx) ? X[m*Kx+k] : X2[m*Kx + k-Kx]    (fused concat)
// X == nullptr  -> operand A is the scratch buffer (sel ? g_A1g : g_A1)
// MODE 0: Out(scratch, by sel) = relu(acc + bias)            (layer 1)
// MODE 1: accumulate sum(mu * (Y - ymean[sel])) into g_acc   (layer 2, mu never stored)
template<int BM, int BN, int BK, int TM, int TN, int MODE>
__global__ void gemm_kernel(const float* __restrict__ X, const float* __restrict__ X2, int Kx,
                            const float* __restrict__ W, const float* __restrict__ Bias,
                            const float* __restrict__ Y, int sel,
                            int M, int N, int K)
{
    constexpr int THREADS = (BM / TM) * (BN / TN);   // 256 for all configs used
    __shared__ float As[BM][BK + 1];
    __shared__ float Bs[BK][BN];

    const float* Xa = X ? X : (sel ? g_A1g : g_A1);
    const float* Xb = X ? X2 : Xa;

    const int tid = threadIdx.x;
    const int tx  = tid % (BN / TN);
    const int ty  = tid / (BN / TN);
    const int m0  = blockIdx.y * BM;
    const int n0  = blockIdx.x * BN;

    float acc[TM][TN] = {};

    for (int k0 = 0; k0 < K; k0 += BK) {
        // A tile [BM x BK]: float4 loads along k (Kx, k0, BK all multiples of 4;
        // the concat boundary Kx is a multiple of BK so a float4 never straddles it)
        #pragma unroll
        for (int idx = tid; idx < BM * (BK / 4); idx += THREADS) {
            int m  = idx / (BK / 4);
            int kq = idx % (BK / 4);
            int gk = k0 + kq * 4;
            const float* src = (gk < Kx) ? &Xa[(m0 + m) * Kx + gk]
                                         : &Xb[(m0 + m) * Kx + gk - Kx];
            float4 v = *reinterpret_cast<const float4*>(src);
            As[m][kq * 4 + 0] = v.x;
            As[m][kq * 4 + 1] = v.y;
            As[m][kq * 4 + 2] = v.z;
            As[m][kq * 4 + 3] = v.w;
        }
        // B tile [BK x BN]: float4 loads along n (N, n0, BN multiples of 4)
        #pragma unroll
        for (int idx = tid; idx < BK * (BN / 4); idx += THREADS) {
            int k  = idx / (BN / 4);
            int nq = idx % (BN / 4);
            float4 v = *reinterpret_cast<const float4*>(&W[(k0 + k) * N + n0 + nq * 4]);
            *reinterpret_cast<float4*>(&Bs[k][nq * 4]) = v;
        }
        __syncthreads();

        #pragma unroll
        for (int kk = 0; kk < BK; ++kk) {
            float rm[TM], rn[TN];
            #pragma unroll
            for (int i = 0; i < TM; ++i) rm[i] = As[ty * TM + i][kk];
            #pragma unroll
            for (int j = 0; j < TN; ++j) rn[j] = Bs[kk][tx * TN + j];
            #pragma unroll
            for (int i = 0; i < TM; ++i)
                #pragma unroll
                for (int j = 0; j < TN; ++j)
                    acc[i][j] += rm[i] * rn[j];
        }
        __syncthreads();
    }

    if (MODE == 0) {
        float* Out = sel ? g_A1g : g_A1;
        #pragma unroll
        for (int i = 0; i < TM; ++i) {
            int gm = m0 + ty * TM + i;
            #pragma unroll
            for (int j = 0; j < TN; ++j) {
                int gn = n0 + tx * TN + j;
                float v = acc[i][j] + Bias[gn];
                Out[gm * N + gn] = v > 0.f ? v : 0.f;
            }
        }
    } else {
        const float* ym = g_ymean + sel * DIM;
        float local = 0.f;
        #pragma unroll
        for (int i = 0; i < TM; ++i) {
            int gm = m0 + ty * TM + i;
            #pragma unroll
            for (int j = 0; j < TN; ++j) {
                int gn = n0 + tx * TN + j;
                float mu = acc[i][j] + Bias[gn];
                local += mu * (Y[gm * N + gn] - ym[gn]);
            }
        }
        __shared__ double red[THREADS];
        red[tid] = (double)local;
        __syncthreads();
        #pragma unroll
        for (int s = THREADS / 2; s > 0; s >>= 1) {
            if (tid < s) red[tid] += red[tid + s];
            __syncthreads();
        }
        if (tid == 0) atomicAdd(&g_acc, red[0]);
    }
}

// ----------------------------------------------------------------------------
__global__ void finish_kernel(float* out)
{
    out[0] = (float)(g_acc * (1.0 / NROWS));
}

// ----------------------------------------------------------------------------
extern "C" void kernel_launch(void* const* d_in, const int* in_sizes, int n_in,
                              void* d_out, int out_size)
{
    const float* H   = (const float*)d_in[0];
    const float* P   = (const float*)d_in[1];
    const float* G   = (const float*)d_in[2];
    const float* W1  = (const float*)d_in[3];
    const float* b1  = (const float*)d_in[4];
    const float* W2  = (const float*)d_in[5];
    const float* b2  = (const float*)d_in[6];
    const float* W1g = (const float*)d_in[7];
    const float* b1g = (const float*)d_in[8];
    const float* W2g = (const float*)d_in[9];
    const float* b2g = (const float*)d_in[10];
    float* out = (float*)d_out;

    // 1) column means + zero accumulator
    init_kernel<<<2, 256>>>(P, G);

    // 2) layer-1 GEMMs: [1024 x K] @ [K x 512] -> relu -> scratch(sel)
    gemm_kernel<64, 64, 16, 4, 4, 0><<<dim3(HID / 64, NROWS / 64), 256>>>(
        H, H, DIM, W1, b1, nullptr, 0, NROWS, HID, DIM);

    gemm_kernel<64, 64, 16, 4, 4, 0><<<dim3(HID / 64, NROWS / 64), 256>>>(
        H, P, DIM, W1g, b1g, nullptr, 1, NROWS, HID, 2 * DIM);

    // 3) layer-2 GEMMs fused with CLUB dot-product epilogue (mu never stored)
    gemm_kernel<64, 32, 16, 4, 2, 1><<<dim3(DIM / 32, NROWS / 64), 256>>>(
        nullptr, nullptr, HID, W2, b2, P, 0, NROWS, DIM, HID);

    gemm_kernel<64, 32, 16, 4, 2, 1><<<dim3(DIM / 32, NROWS / 64), 256>>>(
        nullptr, nullptr, HID, W2g, b2g, G, 1, NROWS, DIM, HID);

    // 4) scalar result
    finish_kernel<<<1, 1>>>(out);
}

// round 3
// speedup vs baseline: 1.6698x; 1.6698x over previous
#include <cuda_runtime.h>

#define NROWS 1024
#define DIM   256
#define HID   512

// Scratch (no allocations allowed) -------------------------------------------
__device__ __align__(16) float  g_A1 [NROWS * HID];   // relu(H@W1+b1)
__device__ __align__(16) float  g_A1g[NROWS * HID];   // relu([H,P]@W1g+b1g)
__device__ __align__(16) float  g_ymean[2 * DIM];     // col means: P | G
__device__ double g_acc;

// ============================================================================
// Kernel A: both layer-1 GEMMs (relu) + column means + zero accumulator.
// Blocks 0..255   : problem 0  (H @ W1,  K=256)
// Blocks 256..511 : problem 1  ([H|P] @ W1g, K=512, fused concat)
// Blocks 512..513 : column means of P / G (8-way double accumulation)
// Tiles: BM=64 BN=32 BK=32, TM=4 TN=2, 256 threads.
// ============================================================================
__global__ void __launch_bounds__(256) kA(const float* __restrict__ H,
                                          const float* __restrict__ P,
                                          const float* __restrict__ G,
                                          const float* __restrict__ W1,
                                          const float* __restrict__ b1,
                                          const float* __restrict__ W1g,
                                          const float* __restrict__ b1g)
{
    const int bid = blockIdx.x;
    const int tid = threadIdx.x;

    if (bid >= 512) {                       // ---- means blocks ----
        const float* Y = (bid == 512) ? P : G;
        if (bid == 512 && tid == 0) g_acc = 0.0;
        double s0=0, s1=0, s2=0, s3=0, s4=0, s5=0, s6=0, s7=0;
        for (int j = 0; j < NROWS; j += 8) {
            s0 += (double)Y[(j+0)*DIM + tid];
            s1 += (double)Y[(j+1)*DIM + tid];
            s2 += (double)Y[(j+2)*DIM + tid];
            s3 += (double)Y[(j+3)*DIM + tid];
            s4 += (double)Y[(j+4)*DIM + tid];
            s5 += (double)Y[(j+5)*DIM + tid];
            s6 += (double)Y[(j+6)*DIM + tid];
            s7 += (double)Y[(j+7)*DIM + tid];
        }
        double s = ((s0+s1)+(s2+s3)) + ((s4+s5)+(s6+s7));
        g_ymean[(bid - 512) * DIM + tid] = (float)(s * (1.0 / NROWS));
        return;
    }

    const int prob = bid >> 8;
    const int t    = bid & 255;
    const int m0   = (t >> 4) * 64;
    const int n0   = (t & 15) * 32;
    const float* __restrict__ Xb   = prob ? P    : H;
    const float* __restrict__ W    = prob ? W1g  : W1;
    const float* __restrict__ Bias = prob ? b1g  : b1;
    float*                    Out  = prob ? g_A1g : g_A1;
    const int K = prob ? 2 * DIM : DIM;

    __shared__ float As[64][33];            // +1 pad: conflict-free rd & wr
    __shared__ float Bs[32][32];

    const int tx = tid & 15;                // n-index (16)
    const int ty = tid >> 4;                // m-index (16)
    float acc[4][2] = {};

    for (int k0 = 0; k0 < K; k0 += 32) {
        #pragma unroll
        for (int r = 0; r < 2; ++r) {       // A tile: 512 float4 / 256 thr
            int idx = tid + r * 256;
            int m = idx >> 3, kq = idx & 7;
            int gk = k0 + kq * 4;
            const float* src = (gk < DIM) ? &H [(m0 + m) * DIM + gk]
                                          : &Xb[(m0 + m) * DIM + gk - DIM];
            float4 v = *reinterpret_cast<const float4*>(src);
            As[m][kq*4+0] = v.x; As[m][kq*4+1] = v.y;
            As[m][kq*4+2] = v.z; As[m][kq*4+3] = v.w;
        }
        {                                   // B tile: 256 float4 / 256 thr
            int k = tid >> 3, nq = tid & 7;
            float4 v = *reinterpret_cast<const float4*>(&W[(k0 + k) * HID + n0 + nq*4]);
            *reinterpret_cast<float4*>(&Bs[k][nq*4]) = v;
        }
        __syncthreads();

        #pragma unroll
        for (int kk = 0; kk < 32; ++kk) {
            float rm0 = As[ty*4+0][kk], rm1 = As[ty*4+1][kk];
            float rm2 = As[ty*4+2][kk], rm3 = As[ty*4+3][kk];
            float rn0 = Bs[kk][tx*2+0], rn1 = Bs[kk][tx*2+1];
            acc[0][0] += rm0*rn0; acc[0][1] += rm0*rn1;
            acc[1][0] += rm1*rn0; acc[1][1] += rm1*rn1;
            acc[2][0] += rm2*rn0; acc[2][1] += rm2*rn1;
            acc[3][0] += rm3*rn0; acc[3][1] += rm3*rn1;
        }
        __syncthreads();
    }

    #pragma unroll
    for (int i = 0; i < 4; ++i) {
        int gm = m0 + ty*4 + i;
        #pragma unroll
        for (int j = 0; j < 2; ++j) {
            int gn = n0 + tx*2 + j;
            float v = acc[i][j] + Bias[gn];
            Out[gm * HID + gn] = fmaxf(v, 0.f);
        }
    }
}

// ============================================================================
// Kernel B: both layer-2 GEMMs, split-K x4, fused CLUB epilogue (linear in
// K-partials: chunk 0 carries the bias term). mu is never materialized.
// Grid: 2 probs x 4 chunks x (16 m-tiles x 8 n-tiles) = 1024 blocks.
// ============================================================================
__global__ void __launch_bounds__(256) kB(const float* __restrict__ W2,
                                          const float* __restrict__ b2,
                                          const float* __restrict__ W2g,
                                          const float* __restrict__ b2g,
                                          const float* __restrict__ P,
                                          const float* __restrict__ G)
{
    const int bid = blockIdx.x;
    const int tid = threadIdx.x;
    const int prob  = bid >> 9;
    const int t     = bid & 511;
    const int chunk = t >> 7;
    const int tt    = t & 127;
    const int m0    = (tt >> 3) * 64;
    const int n0    = (tt & 7) * 32;

    const float* __restrict__ A    = prob ? g_A1g : g_A1;   // [1024, 512]
    const float* __restrict__ W    = prob ? W2g   : W2;     // [512, 256]
    const float* __restrict__ Bias = prob ? b2g   : b2;
    const float* __restrict__ Y    = prob ? G     : P;
    const float* __restrict__ ym   = g_ymean + prob * DIM;

    __shared__ float As[64][33];
    __shared__ float Bs[32][32];
    __shared__ double red[8];

    const int tx = tid & 15;
    const int ty = tid >> 4;
    float acc[4][2] = {};

    const int kbeg = chunk * 128;
    for (int k0 = kbeg; k0 < kbeg + 128; k0 += 32) {
        #pragma unroll
        for (int r = 0; r < 2; ++r) {
            int idx = tid + r * 256;
            int m = idx >> 3, kq = idx & 7;
            float4 v = *reinterpret_cast<const float4*>(&A[(m0 + m) * HID + k0 + kq*4]);
            As[m][kq*4+0] = v.x; As[m][kq*4+1] = v.y;
            As[m][kq*4+2] = v.z; As[m][kq*4+3] = v.w;
        }
        {
            int k = tid >> 3, nq = tid & 7;
            float4 v = *reinterpret_cast<const float4*>(&W[(k0 + k) * DIM + n0 + nq*4]);
            *reinterpret_cast<float4*>(&Bs[k][nq*4]) = v;
        }
        __syncthreads();

        #pragma unroll
        for (int kk = 0; kk < 32; ++kk) {
            float rm0 = As[ty*4+0][kk], rm1 = As[ty*4+1][kk];
            float rm2 = As[ty*4+2][kk], rm3 = As[ty*4+3][kk];
            float rn0 = Bs[kk][tx*2+0], rn1 = Bs[kk][tx*2+1];
            acc[0][0] += rm0*rn0; acc[0][1] += rm0*rn1;
            acc[1][0] += rm1*rn0; acc[1][1] += rm1*rn1;
            acc[2][0] += rm2*rn0; acc[2][1] += rm2*rn1;
            acc[3][0] += rm3*rn0; acc[3][1] += rm3*rn1;
        }
        __syncthreads();
    }

    // Fused CLUB dot-product epilogue on this K-partial
    float local = 0.f;
    #pragma unroll
    for (int i = 0; i < 4; ++i) {
        int gm = m0 + ty*4 + i;
        #pragma unroll
        for (int j = 0; j < 2; ++j) {
            int gn = n0 + tx*2 + j;
            float mu = acc[i][j] + (chunk == 0 ? Bias[gn] : 0.f);
            local += mu * (Y[gm * DIM + gn] - ym[gn]);
        }
    }
    // warp shuffle reduce, then 8-slot double reduce, one atomicAdd per block
    #pragma unroll
    for (int off = 16; off > 0; off >>= 1)
        local += __shfl_xor_sync(0xFFFFFFFF, local, off);
    if ((tid & 31) == 0) red[tid >> 5] = (double)local;
    __syncthreads();
    if (tid == 0) {
        double s = ((red[0]+red[1])+(red[2]+red[3])) + ((red[4]+red[5])+(red[6]+red[7]));
        atomicAdd(&g_acc, s);
    }
}

// ----------------------------------------------------------------------------
__global__ void finish_kernel(float* out)
{
    out[0] = (float)(g_acc * (1.0 / NROWS));
}

// ----------------------------------------------------------------------------
extern "C" void kernel_launch(void* const* d_in, const int* in_sizes, int n_in,
                              void* d_out, int out_size)
{
    const float* H   = (const float*)d_in[0];
    const float* P   = (const float*)d_in[1];
    const float* G   = (const float*)d_in[2];
    const float* W1  = (const float*)d_in[3];
    const float* b1  = (const float*)d_in[4];
    const float* W2  = (const float*)d_in[5];
    const float* b2  = (const float*)d_in[6];
    const float* W1g = (const float*)d_in[7];
    const float* b1g = (const float*)d_in[8];
    const float* W2g = (const float*)d_in[9];
    const float* b2g = (const float*)d_in[10];
    float* out = (float*)d_out;

    kA<<<514, 256>>>(H, P, G, W1, b1, W1g, b1g);
    kB<<<1024, 256>>>(W2, b2, W2g, b2g, P, G);
    finish_kernel<<<1, 1>>>(out);
}

// round 4
// speedup vs baseline: 1.8100x; 1.0840x over previous
#include <cuda_runtime.h>

#define NROWS 1024
#define DIM   256
#define HID   512

// Scratch -------------------------------------------------------------------
__device__ __align__(16) float  g_A1  [NROWS * HID];  // relu(H@W1+b1)
__device__ __align__(16) float  g_A1g [NROWS * HID];  // relu([H|P]@W1g+b1g)
__device__ __align__(16) float  g_ypart[2 * 32 * DIM]; // partial col sums: P | G
__device__ double g_acc;

// ============================================================================
// GEMM microkernel: BM=32, BN=64, BK=16, 128 threads, TM=4, TN=4.
// AsT[k][m] (pad 36) -> rm is one float4; Bs[k][n] -> rn is one float4.
// Inner step: 2x LDS.128 + 16 FFMA.
// ============================================================================

// Kernel A: blocks 0..63 = means partials (2 tensors x 32 row-chunks),
//           blocks 64..  = layer-1 GEMMs (prob0: H@W1 K=256; prob1: [H|P]@W1g K=512)
__global__ void __launch_bounds__(128) kA(const float* __restrict__ H,
                                          const float* __restrict__ P,
                                          const float* __restrict__ G,
                                          const float* __restrict__ W1,
                                          const float* __restrict__ b1,
                                          const float* __restrict__ W1g,
                                          const float* __restrict__ b1g)
{
    const int bid = blockIdx.x;
    const int tid = threadIdx.x;

    if (bid < 64) {                               // ---- means partial blocks ----
        if (bid == 0 && tid == 0) g_acc = 0.0;
        const int which = bid >> 5;               // 0 = P, 1 = G
        const int part  = bid & 31;
        const float* Y  = which ? G : P;
        const int r0 = part * 32;
        #pragma unroll
        for (int h = 0; h < 2; ++h) {             // 128 thr x 2 = 256 cols
            int d = tid + h * 128;
            float s = 0.f;
            #pragma unroll 8
            for (int r = 0; r < 32; ++r) s += Y[(r0 + r) * DIM + d];
            g_ypart[(which * 32 + part) * DIM + d] = s;
        }
        return;
    }

    const int g    = bid - 64;
    const int prob = g >> 8;                      // 256 blocks per problem
    const int t    = g & 255;
    const int m0   = (t >> 3) * 32;               // 32 m-tiles
    const int n0   = (t & 7) * 64;                // 8 n-tiles
    const float* __restrict__ Xb   = prob ? P     : H;
    const float* __restrict__ W    = prob ? W1g   : W1;
    const float* __restrict__ Bias = prob ? b1g   : b1;
    float*                    Out  = prob ? g_A1g : g_A1;
    const int K = prob ? 2 * DIM : DIM;

    __shared__ float AsT[16][36];                 // transposed A tile
    __shared__ float Bs [16][64];

    const int tx = tid & 15;                      // n (16 groups of 4)
    const int ty = tid >> 4;                      // m (8 groups of 4)
    float acc[4][4] = {};

    // load-thread mapping
    const int a_kq = tid & 3;                     // float4 along k
    const int a_m  = tid >> 2;                    // row 0..31
    const int b_k  = tid >> 4;                    // Bs: 2 rows per thread pass
    const int b_nq = tid & 15;

    for (int k0 = 0; k0 < K; k0 += 16) {
        {   // A tile 32x16: 128 float4 loads, transposed store
            int gk = k0 + a_kq * 4;
            const float* src = (gk < DIM) ? &H [(m0 + a_m) * DIM + gk]
                                          : &Xb[(m0 + a_m) * DIM + gk - DIM];
            float4 v = *reinterpret_cast<const float4*>(src);
            AsT[a_kq*4+0][a_m] = v.x;
            AsT[a_kq*4+1][a_m] = v.y;
            AsT[a_kq*4+2][a_m] = v.z;
            AsT[a_kq*4+3][a_m] = v.w;
        }
        #pragma unroll
        for (int r = 0; r < 2; ++r) {             // B tile 16x64: 256 float4
            int k = b_k + r * 8;
            float4 v = *reinterpret_cast<const float4*>(&W[(k0 + k) * HID + n0 + b_nq*4]);
            *reinterpret_cast<float4*>(&Bs[k][b_nq*4]) = v;
        }
        __syncthreads();

        #pragma unroll
        for (int kk = 0; kk < 16; ++kk) {
            float4 rm = *reinterpret_cast<const float4*>(&AsT[kk][ty*4]);
            float4 rn = *reinterpret_cast<const float4*>(&Bs [kk][tx*4]);
            acc[0][0] += rm.x*rn.x; acc[0][1] += rm.x*rn.y; acc[0][2] += rm.x*rn.z; acc[0][3] += rm.x*rn.w;
            acc[1][0] += rm.y*rn.x; acc[1][1] += rm.y*rn.y; acc[1][2] += rm.y*rn.z; acc[1][3] += rm.y*rn.w;
            acc[2][0] += rm.z*rn.x; acc[2][1] += rm.z*rn.y; acc[2][2] += rm.z*rn.z; acc[2][3] += rm.z*rn.w;
            acc[3][0] += rm.w*rn.x; acc[3][1] += rm.w*rn.y; acc[3][2] += rm.w*rn.z; acc[3][3] += rm.w*rn.w;
        }
        __syncthreads();
    }

    #pragma unroll
    for (int i = 0; i < 4; ++i) {
        int gm = m0 + ty*4 + i;
        #pragma unroll
        for (int j = 0; j < 4; ++j) {
            int gn = n0 + tx*4 + j;
            float v = acc[i][j] + Bias[gn];
            Out[gm * HID + gn] = fmaxf(v, 0.f);
        }
    }
}

// ============================================================================
// Kernel B: layer-2 GEMMs, split-K x2, fused CLUB epilogue.
// Grid: 2 probs x 2 chunks x (32 m-tiles x 4 n-tiles) = 512 blocks.
// ym reduced on the fly from g_ypart (chunk-0 blocks carry bias).
// ============================================================================
__global__ void __launch_bounds__(128) kB(const float* __restrict__ W2,
                                          const float* __restrict__ b2,
                                          const float* __restrict__ W2g,
                                          const float* __restrict__ b2g,
                                          const float* __restrict__ P,
                                          const float* __restrict__ G)
{
    const int bid = blockIdx.x;
    const int tid = threadIdx.x;
    const int prob  = bid >> 8;
    const int t     = bid & 255;
    const int chunk = t >> 7;                     // 0 or 1 (K halves of 256)
    const int tt    = t & 127;
    const int m0    = (tt >> 2) * 32;
    const int n0    = (tt & 3) * 64;

    const float* __restrict__ A    = prob ? g_A1g : g_A1;   // [1024, 512]
    const float* __restrict__ W    = prob ? W2g   : W2;     // [512, 256]
    const float* __restrict__ Bias = prob ? b2g   : b2;
    const float* __restrict__ Y    = prob ? G     : P;

    __shared__ float AsT[16][36];
    __shared__ float Bs [16][64];
    __shared__ float ym_s[64];
    __shared__ double red[4];

    // reduce ym for this block's 64 columns from 32 partials
    if (tid < 64) {
        float s = 0.f;
        #pragma unroll 8
        for (int b = 0; b < 32; ++b) s += g_ypart[(prob * 32 + b) * DIM + n0 + tid];
        ym_s[tid] = s * (1.0f / NROWS);
    }

    const int tx = tid & 15;
    const int ty = tid >> 4;
    float acc[4][4] = {};

    const int a_kq = tid & 3;
    const int a_m  = tid >> 2;
    const int b_k  = tid >> 4;
    const int b_nq = tid & 15;

    const int kbeg = chunk * 256;
    for (int k0 = kbeg; k0 < kbeg + 256; k0 += 16) {
        {
            float4 v = *reinterpret_cast<const float4*>(&A[(m0 + a_m) * HID + k0 + a_kq*4]);
            AsT[a_kq*4+0][a_m] = v.x;
            AsT[a_kq*4+1][a_m] = v.y;
            AsT[a_kq*4+2][a_m] = v.z;
            AsT[a_kq*4+3][a_m] = v.w;
        }
        #pragma unroll
        for (int r = 0; r < 2; ++r) {
            int k = b_k + r * 8;
            float4 v = *reinterpret_cast<const float4*>(&W[(k0 + k) * DIM + n0 + b_nq*4]);
            *reinterpret_cast<float4*>(&Bs[k][b_nq*4]) = v;
        }
        __syncthreads();

        #pragma unroll
        for (int kk = 0; kk < 16; ++kk) {
            float4 rm = *reinterpret_cast<const float4*>(&AsT[kk][ty*4]);
            float4 rn = *reinterpret_cast<const float4*>(&Bs [kk][tx*4]);
            acc[0][0] += rm.x*rn.x; acc[0][1] += rm.x*rn.y; acc[0][2] += rm.x*rn.z; acc[0][3] += rm.x*rn.w;
            acc[1][0] += rm.y*rn.x; acc[1][1] += rm.y*rn.y; acc[1][2] += rm.y*rn.z; acc[1][3] += rm.y*rn.w;
            acc[2][0] += rm.z*rn.x; acc[2][1] += rm.z*rn.y; acc[2][2] += rm.z*rn.z; acc[2][3] += rm.z*rn.w;
            acc[3][0] += rm.w*rn.x; acc[3][1] += rm.w*rn.y; acc[3][2] += rm.w*rn.z; acc[3][3] += rm.w*rn.w;
        }
        __syncthreads();
    }

    // fused CLUB dot-product on this K-partial (linear in partials; bias on chunk 0)
    float local = 0.f;
    #pragma unroll
    for (int i = 0; i < 4; ++i) {
        int gm = m0 + ty*4 + i;
        #pragma unroll
        for (int j = 0; j < 4; ++j) {
            int gn = n0 + tx*4 + j;
            float mu = acc[i][j] + (chunk == 0 ? Bias[gn] : 0.f);
            local += mu * (Y[gm * DIM + gn] - ym_s[tx*4 + j]);
        }
    }
    #pragma unroll
    for (int off = 16; off > 0; off >>= 1)
        local += __shfl_xor_sync(0xFFFFFFFF, local, off);
    if ((tid & 31) == 0) red[tid >> 5] = (double)local;
    __syncthreads();
    if (tid == 0)
        atomicAdd(&g_acc, (red[0] + red[1]) + (red[2] + red[3]));
}

// ----------------------------------------------------------------------------
__global__ void finish_kernel(float* out)
{
    out[0] = (float)(g_acc * (1.0 / NROWS));
}

// ----------------------------------------------------------------------------
extern "C" void kernel_launch(void* const* d_in, const int* in_sizes, int n_in,
                              void* d_out, int out_size)
{
    const float* H   = (const float*)d_in[0];
    const float* P   = (const float*)d_in[1];
    const float* G   = (const float*)d_in[2];
    const float* W1  = (const float*)d_in[3];
    const float* b1  = (const float*)d_in[4];
    const float* W2  = (const float*)d_in[5];
    const float* b2  = (const float*)d_in[6];
    const float* W1g = (const float*)d_in[7];
    const float* b1g = (const float*)d_in[8];
    const float* W2g = (const float*)d_in[9];
    const float* b2g = (const float*)d_in[10];
    float* out = (float*)d_out;

    kA<<<576, 128>>>(H, P, G, W1, b1, W1g, b1g);
    kB<<<512, 128>>>(W2, b2, W2g, b2g, P, G);
    finish_kernel<<<1, 1>>>(out);
}

// round 5
// speedup vs baseline: 2.0363x; 1.1250x over previous
#include <cuda_runtime.h>

#define NROWS 1024
#define DIM   256
#define HID   512
#define BM 32
#define BN 64
#define BK 32

// Scratch -------------------------------------------------------------------
__device__ __align__(16) float  g_A1  [NROWS * HID];   // relu(H@W1+b1)
__device__ __align__(16) float  g_A1g [NROWS * HID];   // relu([H|P]@W1g+b1g)
__device__ __align__(16) float  g_ypart[2 * 32 * DIM]; // partial col sums: P | G
__device__ double g_acc;

// ============================================================================
// Kernel A: blocks 0..63 = column-mean partials, blocks 64.. = layer-1 GEMMs.
// GEMM: BM=32 BN=64 BK=32, 128 thr, TM=4 TN=4, double-buffered smem,
// one __syncthreads per k-tile, prefetch global->regs overlapped with compute.
// ============================================================================
__global__ void __launch_bounds__(128) kA(const float* __restrict__ H,
                                          const float* __restrict__ P,
                                          const float* __restrict__ G,
                                          const float* __restrict__ W1,
                                          const float* __restrict__ b1,
                                          const float* __restrict__ W1g,
                                          const float* __restrict__ b1g)
{
    const int bid = blockIdx.x;
    const int tid = threadIdx.x;

    if (bid < 64) {                               // ---- means partial blocks ----
        if (bid == 0 && tid == 0) g_acc = 0.0;
        const int which = bid >> 5;               // 0 = P, 1 = G
        const int part  = bid & 31;
        const float* Y  = which ? G : P;
        const int r0 = part * 32;
        #pragma unroll
        for (int h = 0; h < 2; ++h) {
            int d = tid + h * 128;
            float s = 0.f;
            #pragma unroll 8
            for (int r = 0; r < 32; ++r) s += Y[(r0 + r) * DIM + d];
            g_ypart[(which * 32 + part) * DIM + d] = s;
        }
        return;
    }

    const int g    = bid - 64;
    const int prob = g >> 8;                      // 256 blocks / problem
    const int t    = g & 255;
    const int m0   = (t >> 3) * BM;               // 32 m-tiles
    const int n0   = (t & 7) * BN;                // 8  n-tiles
    const float* __restrict__ Xb   = prob ? P     : H;
    const float* __restrict__ W    = prob ? W1g   : W1;
    const float* __restrict__ Bias = prob ? b1g   : b1;
    float*                    Out  = prob ? g_A1g : g_A1;
    const int niter = (prob ? 2 * DIM : DIM) / BK; // 16 or 8

    __shared__ float AsT[2][BK][36];
    __shared__ float Bs [2][BK][BN];

    const int a_m  = tid >> 2, a_kq = tid & 3;    // A: 2 float4/thread
    const int b_k  = tid >> 4, b_nq = tid & 15;   // B: 4 float4/thread
    const int tx   = tid & 15, ty   = tid >> 4;

    float4 ra[2], rb[4];
    float acc[4][4] = {};

    // ---- prologue: tile 0 ----
    #pragma unroll
    for (int r = 0; r < 2; ++r) {
        int gk = (a_kq + r * 4) * 4;
        const float* src = (gk < DIM) ? &H [(m0 + a_m) * DIM + gk]
                                      : &Xb[(m0 + a_m) * DIM + gk - DIM];
        ra[r] = *reinterpret_cast<const float4*>(src);
    }
    #pragma unroll
    for (int r = 0; r < 4; ++r)
        rb[r] = *reinterpret_cast<const float4*>(&W[(b_k + r * 8) * HID + n0 + b_nq * 4]);
    #pragma unroll
    for (int r = 0; r < 2; ++r) {
        int k = (a_kq + r * 4) * 4;
        AsT[0][k+0][a_m] = ra[r].x; AsT[0][k+1][a_m] = ra[r].y;
        AsT[0][k+2][a_m] = ra[r].z; AsT[0][k+3][a_m] = ra[r].w;
    }
    #pragma unroll
    for (int r = 0; r < 4; ++r)
        *reinterpret_cast<float4*>(&Bs[0][b_k + r * 8][b_nq * 4]) = rb[r];
    __syncthreads();

    for (int it = 0; it < niter; ++it) {
        const int cur = it & 1;
        if (it + 1 < niter) {                     // prefetch next tile -> regs
            int k0 = (it + 1) * BK;
            #pragma unroll
            for (int r = 0; r < 2; ++r) {
                int gk = k0 + (a_kq + r * 4) * 4;
                const float* src = (gk < DIM) ? &H [(m0 + a_m) * DIM + gk]
                                              : &Xb[(m0 + a_m) * DIM + gk - DIM];
                ra[r] = *reinterpret_cast<const float4*>(src);
            }
            #pragma unroll
            for (int r = 0; r < 4; ++r)
                rb[r] = *reinterpret_cast<const float4*>(&W[(k0 + b_k + r * 8) * HID + n0 + b_nq * 4]);
        }
        #pragma unroll
        for (int kk = 0; kk < BK; ++kk) {
            float4 rm = *reinterpret_cast<const float4*>(&AsT[cur][kk][ty * 4]);
            float4 rn = *reinterpret_cast<const float4*>(&Bs [cur][kk][tx * 4]);
            acc[0][0] += rm.x*rn.x; acc[0][1] += rm.x*rn.y; acc[0][2] += rm.x*rn.z; acc[0][3] += rm.x*rn.w;
            acc[1][0] += rm.y*rn.x; acc[1][1] += rm.y*rn.y; acc[1][2] += rm.y*rn.z; acc[1][3] += rm.y*rn.w;
            acc[2][0] += rm.z*rn.x; acc[2][1] += rm.z*rn.y; acc[2][2] += rm.z*rn.z; acc[2][3] += rm.z*rn.w;
            acc[3][0] += rm.w*rn.x; acc[3][1] += rm.w*rn.y; acc[3][2] += rm.w*rn.z; acc[3][3] += rm.w*rn.w;
        }
        if (it + 1 < niter) {                     // stage into other buffer
            const int nxt = cur ^ 1;
            #pragma unroll
            for (int r = 0; r < 2; ++r) {
                int k = (a_kq + r * 4) * 4;
                AsT[nxt][k+0][a_m] = ra[r].x; AsT[nxt][k+1][a_m] = ra[r].y;
                AsT[nxt][k+2][a_m] = ra[r].z; AsT[nxt][k+3][a_m] = ra[r].w;
            }
            #pragma unroll
            for (int r = 0; r < 4; ++r)
                *reinterpret_cast<float4*>(&Bs[nxt][b_k + r * 8][b_nq * 4]) = rb[r];
        }
        __syncthreads();
    }

    // ---- relu epilogue, float4 stores ----
    const float4 bv = *reinterpret_cast<const float4*>(&Bias[n0 + tx * 4]);
    #pragma unroll
    for (int i = 0; i < 4; ++i) {
        int gm = m0 + ty * 4 + i;
        float4 o;
        o.x = fmaxf(acc[i][0] + bv.x, 0.f);
        o.y = fmaxf(acc[i][1] + bv.y, 0.f);
        o.z = fmaxf(acc[i][2] + bv.z, 0.f);
        o.w = fmaxf(acc[i][3] + bv.w, 0.f);
        *reinterpret_cast<float4*>(&Out[gm * HID + n0 + tx * 4]) = o;
    }
}

// ============================================================================
// Kernel B: layer-2 GEMMs, split-K x2, fused CLUB epilogue, double-buffered.
// Grid: 2 probs x 2 chunks x (32 m x 4 n) = 512 blocks.
// ============================================================================
__global__ void __launch_bounds__(128) kB(const float* __restrict__ W2,
                                          const float* __restrict__ b2,
                                          const float* __restrict__ W2g,
                                          const float* __restrict__ b2g,
                                          const float* __restrict__ P,
                                          const float* __restrict__ G)
{
    const int bid = blockIdx.x;
    const int tid = threadIdx.x;
    const int prob  = bid >> 8;
    const int t     = bid & 255;
    const int chunk = t >> 7;
    const int tt    = t & 127;
    const int m0    = (tt >> 2) * BM;
    const int n0    = (tt & 3) * BN;

    const float* __restrict__ A    = prob ? g_A1g : g_A1;   // [1024, 512]
    const float* __restrict__ W    = prob ? W2g   : W2;     // [512, 256]
    const float* __restrict__ Bias = prob ? b2g   : b2;
    const float* __restrict__ Y    = prob ? G     : P;

    __shared__ float AsT[2][BK][36];
    __shared__ float Bs [2][BK][BN];
    __shared__ float ym_s[BN];
    __shared__ double red[4];

    if (tid < 64) {                               // ym for this block's columns
        float s = 0.f;
        #pragma unroll 8
        for (int b = 0; b < 32; ++b) s += g_ypart[(prob * 32 + b) * DIM + n0 + tid];
        ym_s[tid] = s * (1.0f / NROWS);
    }

    const int a_m  = tid >> 2, a_kq = tid & 3;
    const int b_k  = tid >> 4, b_nq = tid & 15;
    const int tx   = tid & 15, ty   = tid >> 4;

    float4 ra[2], rb[4];
    float acc[4][4] = {};
    const int kbeg = chunk * 256;
    const int niter = 256 / BK;                   // 8

    #pragma unroll
    for (int r = 0; r < 2; ++r)
        ra[r] = *reinterpret_cast<const float4*>(&A[(m0 + a_m) * HID + kbeg + (a_kq + r * 4) * 4]);
    #pragma unroll
    for (int r = 0; r < 4; ++r)
        rb[r] = *reinterpret_cast<const float4*>(&W[(kbeg + b_k + r * 8) * DIM + n0 + b_nq * 4]);
    #pragma unroll
    for (int r = 0; r < 2; ++r) {
        int k = (a_kq + r * 4) * 4;
        AsT[0][k+0][a_m] = ra[r].x; AsT[0][k+1][a_m] = ra[r].y;
        AsT[0][k+2][a_m] = ra[r].z; AsT[0][k+3][a_m] = ra[r].w;
    }
    #pragma unroll
    for (int r = 0; r < 4; ++r)
        *reinterpret_cast<float4*>(&Bs[0][b_k + r * 8][b_nq * 4]) = rb[r];
    __syncthreads();

    for (int it = 0; it < niter; ++it) {
        const int cur = it & 1;
        if (it + 1 < niter) {
            int k0 = kbeg + (it + 1) * BK;
            #pragma unroll
            for (int r = 0; r < 2; ++r)
                ra[r] = *reinterpret_cast<const float4*>(&A[(m0 + a_m) * HID + k0 + (a_kq + r * 4) * 4]);
            #pragma unroll
            for (int r = 0; r < 4; ++r)
                rb[r] = *reinterpret_cast<const float4*>(&W[(k0 + b_k + r * 8) * DIM + n0 + b_nq * 4]);
        }
        #pragma unroll
        for (int kk = 0; kk < BK; ++kk) {
            float4 rm = *reinterpret_cast<const float4*>(&AsT[cur][kk][ty * 4]);
            float4 rn = *reinterpret_cast<const float4*>(&Bs [cur][kk][tx * 4]);
            acc[0][0] += rm.x*rn.x; acc[0][1] += rm.x*rn.y; acc[0][2] += rm.x*rn.z; acc[0][3] += rm.x*rn.w;
            acc[1][0] += rm.y*rn.x; acc[1][1] += rm.y*rn.y; acc[1][2] += rm.y*rn.z; acc[1][3] += rm.y*rn.w;
            acc[2][0] += rm.z*rn.x; acc[2][1] += rm.z*rn.y; acc[2][2] += rm.z*rn.z; acc[2][3] += rm.z*rn.w;
            acc[3][0] += rm.w*rn.x; acc[3][1] += rm.w*rn.y; acc[3][2] += rm.w*rn.z; acc[3][3] += rm.w*rn.w;
        }
        if (it + 1 < niter) {
            const int nxt = cur ^ 1;
            #pragma unroll
            for (int r = 0; r < 2; ++r) {
                int k = (a_kq + r * 4) * 4;
                AsT[nxt][k+0][a_m] = ra[r].x; AsT[nxt][k+1][a_m] = ra[r].y;
                AsT[nxt][k+2][a_m] = ra[r].z; AsT[nxt][k+3][a_m] = ra[r].w;
            }
            #pragma unroll
            for (int r = 0; r < 4; ++r)
                *reinterpret_cast<float4*>(&Bs[nxt][b_k + r * 8][b_nq * 4]) = rb[r];
        }
        __syncthreads();
    }

    // ---- fused CLUB dot-product on this K-partial (bias rides on chunk 0) ----
    const float4 bv = *reinterpret_cast<const float4*>(&Bias[n0 + tx * 4]);
    const float4 ym = *reinterpret_cast<const float4*>(&ym_s[tx * 4]);
    float local = 0.f;
    #pragma unroll
    for (int i = 0; i < 4; ++i) {
        int gm = m0 + ty * 4 + i;
        float4 yv = *reinterpret_cast<const float4*>(&Y[gm * DIM + n0 + tx * 4]);
        float m0f = acc[i][0] + (chunk == 0 ? bv.x : 0.f);
        float m1f = acc[i][1] + (chunk == 0 ? bv.y : 0.f);
        float m2f = acc[i][2] + (chunk == 0 ? bv.z : 0.f);
        float m3f = acc[i][3] + (chunk == 0 ? bv.w : 0.f);
        local += m0f * (yv.x - ym.x) + m1f * (yv.y - ym.y)
               + m2f * (yv.z - ym.z) + m3f * (yv.w - ym.w);
    }
    #pragma unroll
    for (int off = 16; off > 0; off >>= 1)
        local += __shfl_xor_sync(0xFFFFFFFF, local, off);
    if ((tid & 31) == 0) red[tid >> 5] = (double)local;
    __syncthreads();
    if (tid == 0)
        atomicAdd(&g_acc, (red[0] + red[1]) + (red[2] + red[3]));
}

// ----------------------------------------------------------------------------
__global__ void finish_kernel(float* out)
{
    out[0] = (float)(g_acc * (1.0 / NROWS));
}

// ----------------------------------------------------------------------------
extern "C" void kernel_launch(void* const* d_in, const int* in_sizes, int n_in,
                              void* d_out, int out_size)
{
    const float* H   = (const float*)d_in[0];
    const float* P   = (const float*)d_in[1];
    const float* G   = (const float*)d_in[2];
    const float* W1  = (const float*)d_in[3];
    const float* b1  = (const float*)d_in[4];
    const float* W2  = (const float*)d_in[5];
    const float* b2  = (const float*)d_in[6];
    const float* W1g = (const float*)d_in[7];
    const float* b1g = (const float*)d_in[8];
    const float* W2g = (const float*)d_in[9];
    const float* b2g = (const float*)d_in[10];
    float* out = (float*)d_out;

    kA<<<576, 128>>>(H, P, G, W1, b1, W1g, b1g);
    kB<<<512, 128>>>(W2, b2, W2g, b2g, P, G);
    finish_kernel<<<1, 1>>>(out);
}

// round 7
// speedup vs baseline: 2.8348x; 1.3921x over previous
#include <cuda_runtime.h>
#include <cuda_bf16.h>
#include <cstdint>

#define NROWS 1024
#define DIM   256
#define HID   512
#define RS    72          // smem row stride in bf16 (144B = 36 banks, conflict-free frags)

// ============================ device scratch =================================
__device__ __align__(16) __nv_bfloat16 g_Xh[2][NROWS * DIM];     // H, P (hi)
__device__ __align__(16) __nv_bfloat16 g_Xl[2][NROWS * DIM];     // H, P (lo)
__device__ __align__(16) __nv_bfloat16 g_W1t_h [HID * DIM],      g_W1t_l [HID * DIM];      // [512n][256k]
__device__ __align__(16) __nv_bfloat16 g_W1gt_h[HID * 2 * DIM],  g_W1gt_l[HID * 2 * DIM];  // [512n][512k]
__device__ __align__(16) __nv_bfloat16 g_W2t_h [DIM * HID],      g_W2t_l [DIM * HID];      // [256n][512k]
__device__ __align__(16) __nv_bfloat16 g_W2gt_h[DIM * HID],      g_W2gt_l[DIM * HID];
__device__ __align__(16) __nv_bfloat16 g_A1h[2][NROWS * HID],    g_A1l[2][NROWS * HID];
__device__ __align__(16) float  g_ypart[2 * 32 * DIM];
__device__ double g_acc;

__device__ __forceinline__ void cvt2(float v0, float v1, uint32_t& hp, uint32_t& lp) {
    __nv_bfloat16 h0 = __float2bfloat16(v0);
    __nv_bfloat16 h1 = __float2bfloat16(v1);
    __nv_bfloat16 l0 = __float2bfloat16(v0 - __bfloat162float(h0));
    __nv_bfloat16 l1 = __float2bfloat16(v1 - __bfloat162float(h1));
    hp = ((uint32_t)__bfloat16_as_ushort(h1) << 16) | __bfloat16_as_ushort(h0);
    lp = ((uint32_t)__bfloat16_as_ushort(l1) << 16) | __bfloat16_as_ushort(l0);
}

__device__ __forceinline__ uint32_t lds32(const __nv_bfloat16* p) {
    return *reinterpret_cast<const uint32_t*>(p);
}

__device__ __forceinline__ void mma16816(float* c, const uint32_t a0, const uint32_t a1,
                                         const uint32_t a2, const uint32_t a3,
                                         const uint32_t b0, const uint32_t b1) {
    asm volatile(
        "mma.sync.aligned.m16n8k16.row.col.f32.bf16.bf16.f32 "
        "{%0,%1,%2,%3}, {%4,%5,%6,%7}, {%8,%9}, {%0,%1,%2,%3};"
        : "+f"(c[0]), "+f"(c[1]), "+f"(c[2]), "+f"(c[3])
        : "r"(a0), "r"(a1), "r"(a2), "r"(a3), "r"(b0), "r"(b1));
}

// ============================================================================
// kPrep: split X -> bf16 hi/lo; transpose+split weights to [n][k]; means partials.
// grid = 1216 x 256
// ============================================================================
__global__ void __launch_bounds__(256) kPrep(const float* __restrict__ H,
                                             const float* __restrict__ P,
                                             const float* __restrict__ G,
                                             const float* __restrict__ W1,
                                             const float* __restrict__ W1g,
                                             const float* __restrict__ W2,
                                             const float* __restrict__ W2g)
{
    const int bid = blockIdx.x, tid = threadIdx.x;
    if (bid == 0 && tid == 0) g_acc = 0.0;

    if (bid < 512) {                       // ---- X split: 2 x 256 blocks ----
        const int which = bid >> 8;
        const float* X = which ? P : H;
        const int base = (bid & 255) * 1024 + tid * 4;
        float4 v = *reinterpret_cast<const float4*>(&X[base]);
        uint32_t h0, l0, h1, l1;
        cvt2(v.x, v.y, h0, l0);
        cvt2(v.z, v.w, h1, l1);
        *reinterpret_cast<uint2*>(&g_Xh[which][base]) = make_uint2(h0, h1);
        *reinterpret_cast<uint2*>(&g_Xl[which][base]) = make_uint2(l0, l1);
        return;
    }

    if (bid < 1152) {                      // ---- weight transpose+split ----
        int t = bid - 512;
        const float* src; __nv_bfloat16 *dh, *dl; int K, N, kt, nt;
        if (t < 128)      { src = W1;  dh = g_W1t_h;  dl = g_W1t_l;  K = 256; N = 512; kt = t >> 4; nt = t & 15; }
        else if (t < 384) { t -= 128; src = W1g; dh = g_W1gt_h; dl = g_W1gt_l; K = 512; N = 512; kt = t >> 4; nt = t & 15; }
        else if (t < 512) { t -= 384; src = W2;  dh = g_W2t_h;  dl = g_W2t_l;  K = 512; N = 256; kt = t >> 3; nt = t & 7; }
        else              { t -= 512; src = W2g; dh = g_W2gt_h; dl = g_W2gt_l; K = 512; N = 256; kt = t >> 3; nt = t & 7; }
        const int k0 = kt * 32, n0 = nt * 32;

        __shared__ float tile[32][33];
        {
            int r = tid >> 3, c4 = tid & 7;
            float4 v = *reinterpret_cast<const float4*>(&src[(k0 + r) * N + n0 + c4 * 4]);
            tile[r][c4*4+0] = v.x; tile[r][c4*4+1] = v.y;
            tile[r][c4*4+2] = v.z; tile[r][c4*4+3] = v.w;
        }
        __syncthreads();
        {
            int nr = tid >> 3, kc = (tid & 7) * 4;
            uint32_t h0, l0, h1, l1;
            cvt2(tile[kc+0][nr], tile[kc+1][nr], h0, l0);
            cvt2(tile[kc+2][nr], tile[kc+3][nr], h1, l1);
            size_t o = (size_t)(n0 + nr) * K + k0 + kc;
            *reinterpret_cast<uint2*>(&dh[o]) = make_uint2(h0, h1);
            *reinterpret_cast<uint2*>(&dl[o]) = make_uint2(l0, l1);
        }
        return;
    }

    {                                      // ---- means partials: 64 blocks ----
        const int t = bid - 1152;
        const int which = t >> 5, part = t & 31;
        const float* Y = which ? G : P;
        const int r0 = part * 32;
        float s = 0.f;
        #pragma unroll 8
        for (int r = 0; r < 32; ++r) s += Y[(r0 + r) * DIM + tid];
        g_ypart[(which * 32 + part) * DIM + tid] = s;
    }
}

// ============================================================================
// HMMA tile core: CTA 64x64, 4 warps (2x2 of 32x32 warp tiles), BK=64.
// 3-product bf16 split: Ah*Bh + Ah*Bl + Al*Bh  -> fp32 acc.
// acc layout: acc[mi][nj][4] per warp.
// ============================================================================
struct TileSmem {
    __nv_bfloat16 Ah[64 * RS];
    __nv_bfloat16 Al[64 * RS];
    __nv_bfloat16 Bh[64 * RS];
    __nv_bfloat16 Bl[64 * RS];
};

// load one 64x64 bf16 tile pair (hi/lo) into smem, src row stride = ld
__device__ __forceinline__ void load_pair(__nv_bfloat16* dh, __nv_bfloat16* dl,
                                          const __nv_bfloat16* __restrict__ sh,
                                          const __nv_bfloat16* __restrict__ sl,
                                          int row0, int ld, int k0, int tid)
{
    #pragma unroll
    for (int i = 0; i < 8; ++i) {          // 1024 uint2 / 128 threads
        int idx = tid + i * 128;
        int row = idx >> 4, w = idx & 15;
        size_t src = (size_t)(row0 + row) * ld + k0 + w * 4;
        *reinterpret_cast<uint2*>(&dh[row * RS + w * 4]) = *reinterpret_cast<const uint2*>(&sh[src]);
        *reinterpret_cast<uint2*>(&dl[row * RS + w * 4]) = *reinterpret_cast<const uint2*>(&sl[src]);
    }
}

// consume the loaded chunk: 4 k16 steps
__device__ __forceinline__ void consume(const TileSmem& s, float acc[2][4][4],
                                        int wm, int wn, int lane)
{
    const int qr = lane >> 2;              // 0..7
    const int qc = (lane & 3) * 2;         // 0,2,4,6
    #pragma unroll
    for (int ks = 0; ks < 4; ++ks) {
        const int kb = ks * 16 + qc;
        uint32_t ah[2][4], al[2][4];
        #pragma unroll
        for (int mi = 0; mi < 2; ++mi) {
            int r0 = wm * 32 + mi * 16 + qr;
            ah[mi][0] = lds32(&s.Ah[(r0    ) * RS + kb    ]);
            ah[mi][1] = lds32(&s.Ah[(r0 + 8) * RS + kb    ]);
            ah[mi][2] = lds32(&s.Ah[(r0    ) * RS + kb + 8]);
            ah[mi][3] = lds32(&s.Ah[(r0 + 8) * RS + kb + 8]);
            al[mi][0] = lds32(&s.Al[(r0    ) * RS + kb    ]);
            al[mi][1] = lds32(&s.Al[(r0 + 8) * RS + kb    ]);
            al[mi][2] = lds32(&s.Al[(r0    ) * RS + kb + 8]);
            al[mi][3] = lds32(&s.Al[(r0 + 8) * RS + kb + 8]);
        }
        uint32_t bh[4][2], bl[4][2];
        #pragma unroll
        for (int nj = 0; nj < 4; ++nj) {
            int n = wn * 32 + nj * 8 + qr;
            bh[nj][0] = lds32(&s.Bh[n * RS + kb    ]);
            bh[nj][1] = lds32(&s.Bh[n * RS + kb + 8]);
            bl[nj][0] = lds32(&s.Bl[n * RS + kb    ]);
            bl[nj][1] = lds32(&s.Bl[n * RS + kb + 8]);
        }
        #pragma unroll
        for (int mi = 0; mi < 2; ++mi)
            #pragma unroll
            for (int nj = 0; nj < 4; ++nj) {
                mma16816(acc[mi][nj], ah[mi][0], ah[mi][1], ah[mi][2], ah[mi][3], bh[nj][0], bh[nj][1]);
                mma16816(acc[mi][nj], ah[mi][0], ah[mi][1], ah[mi][2], ah[mi][3], bl[nj][0], bl[nj][1]);
                mma16816(acc[mi][nj], al[mi][0], al[mi][1], al[mi][2], al[mi][3], bh[nj][0], bh[nj][1]);
            }
    }
}

// ============================================================================
// kGemm1: layer-1 (relu, re-split hi/lo). 256 CTAs: prob(2) x m(16) x n(8).
// ============================================================================
__global__ void __launch_bounds__(128) kGemm1(const float* __restrict__ b1,
                                              const float* __restrict__ b1g)
{
    __shared__ TileSmem s;
    const int tid  = threadIdx.x;
    const int lane = tid & 31, wrp = tid >> 5;
    const int wm   = wrp >> 1, wn = wrp & 1;
    const int bid  = blockIdx.x;
    const int prob = bid >> 7, t = bid & 127;
    const int m0   = (t >> 3) * 64, n0 = (t & 7) * 64;

    const __nv_bfloat16* Wh = prob ? g_W1gt_h : g_W1t_h;
    const __nv_bfloat16* Wl = prob ? g_W1gt_l : g_W1t_l;
    const int K = prob ? 2 * DIM : DIM;

    float acc[2][4][4] = {};
    for (int k0 = 0; k0 < K; k0 += 64) {
        const int xi = (k0 < DIM) ? 0 : 1;           // concat: H then P
        load_pair(s.Ah, s.Al, g_Xh[xi], g_Xl[xi], m0, DIM, k0 & (DIM - 1), tid);
        load_pair(s.Bh, s.Bl, Wh, Wl, n0, K, k0, tid);
        __syncthreads();
        consume(s, acc, wm, wn, lane);
        __syncthreads();
    }

    const float* Bias = prob ? b1g : b1;
    __nv_bfloat16* Oh = g_A1h[prob];
    __nv_bfloat16* Ol = g_A1l[prob];
    const int qr = lane >> 2, qc = (lane & 3) * 2;
    #pragma unroll
    for (int mi = 0; mi < 2; ++mi) {
        #pragma unroll
        for (int nj = 0; nj < 4; ++nj) {
            int row = m0 + wm * 32 + mi * 16 + qr;
            int col = n0 + wn * 32 + nj * 8 + qc;
            float bz0 = Bias[col], bz1 = Bias[col + 1];
            uint32_t hp, lp;
            cvt2(fmaxf(acc[mi][nj][0] + bz0, 0.f), fmaxf(acc[mi][nj][1] + bz1, 0.f), hp, lp);
            *reinterpret_cast<uint32_t*>(&Oh[(size_t)row * HID + col]) = hp;
            *reinterpret_cast<uint32_t*>(&Ol[(size_t)row * HID + col]) = lp;
            cvt2(fmaxf(acc[mi][nj][2] + bz0, 0.f), fmaxf(acc[mi][nj][3] + bz1, 0.f), hp, lp);
            *reinterpret_cast<uint32_t*>(&Oh[(size_t)(row + 8) * HID + col]) = hp;
            *reinterpret_cast<uint32_t*>(&Ol[(size_t)(row + 8) * HID + col]) = lp;
        }
    }
}

// ============================================================================
// kGemm2: layer-2, split-K x2, fused CLUB epilogue.
// 256 CTAs: prob(2) x m(16) x n(4) x chunk(2).
// ============================================================================
__global__ void __launch_bounds__(128) kGemm2(const float* __restrict__ b2,
                                              const float* __restrict__ b2g,
                                              const float* __restrict__ P,
                                              const float* __restrict__ G)
{
    __shared__ TileSmem s;
    __shared__ float  ym_s[64];
    __shared__ double red[4];
    const int tid  = threadIdx.x;
    const int lane = tid & 31, wrp = tid >> 5;
    const int wm   = wrp >> 1, wn = wrp & 1;
    const int bid  = blockIdx.x;
    const int prob  = bid >> 7, t = bid & 127;
    const int m0    = (t >> 3) * 64;
    const int n0    = ((t >> 1) & 3) * 64;
    const int chunk = t & 1;

    if (tid < 64) {                        // ym for this n-tile
        float sm = 0.f;
        #pragma unroll 8
        for (int b = 0; b < 32; ++b) sm += g_ypart[(prob * 32 + b) * DIM + n0 + tid];
        ym_s[tid] = sm * (1.0f / NROWS);
    }

    const __nv_bfloat16* Ah = g_A1h[prob];
    const __nv_bfloat16* Al = g_A1l[prob];
    const __nv_bfloat16* Wh = prob ? g_W2gt_h : g_W2t_h;
    const __nv_bfloat16* Wl = prob ? g_W2gt_l : g_W2t_l;

    float acc[2][4][4] = {};
    const int kbeg = chunk * 256;
    for (int k0 = kbeg; k0 < kbeg + 256; k0 += 64) {
        load_pair(s.Ah, s.Al, Ah, Al, m0, HID, k0, tid);
        load_pair(s.Bh, s.Bl, Wh, Wl, n0, HID, k0, tid);
        __syncthreads();
        consume(s, acc, wm, wn, lane);
        __syncthreads();
    }

    const float* Bias = prob ? b2g : b2;
    const float* Y    = prob ? G   : P;
    const bool  wb    = (chunk == 0);      // bias rides on chunk 0 (linearity)
    const int qr = lane >> 2, qc = (lane & 3) * 2;
    float local = 0.f;
    #pragma unroll
    for (int mi = 0; mi < 2; ++mi) {
        #pragma unroll
        for (int nj = 0; nj < 4; ++nj) {
            int row = m0 + wm * 32 + mi * 16 + qr;
            int col = n0 + wn * 32 + nj * 8 + qc;
            float bz0 = wb ? Bias[col]     : 0.f;
            float bz1 = wb ? Bias[col + 1] : 0.f;
            float ym0 = ym_s[col - n0], ym1 = ym_s[col - n0 + 1];
            float2 y0 = *reinterpret_cast<const float2*>(&Y[(size_t)row * DIM + col]);
            float2 y1 = *reinterpret_cast<const float2*>(&Y[(size_t)(row + 8) * DIM + col]);
            local += (acc[mi][nj][0] + bz0) * (y0.x - ym0)
                   + (acc[mi][nj][1] + bz1) * (y0.y - ym1)
                   + (acc[mi][nj][2] + bz0) * (y1.x - ym0)
                   + (acc[mi][nj][3] + bz1) * (y1.y - ym1);
        }
    }
    #pragma unroll
    for (int off = 16; off > 0; off >>= 1)
        local += __shfl_xor_sync(0xFFFFFFFF, local, off);
    if (lane == 0) red[wrp] = (double)local;
    __syncthreads();
    if (tid == 0)
        atomicAdd(&g_acc, (red[0] + red[1]) + (red[2] + red[3]));
}

// ----------------------------------------------------------------------------
__global__ void finish_kernel(float* out)
{
    out[0] = (float)(g_acc * (1.0 / NROWS));
}

// ----------------------------------------------------------------------------
extern "C" void kernel_launch(void* const* d_in, const int* in_sizes, int n_in,
                              void* d_out, int out_size)
{
    const float* H   = (const float*)d_in[0];
    const float* P   = (const float*)d_in[1];
    const float* G   = (const float*)d_in[2];
    const float* W1  = (const float*)d_in[3];
    const float* b1  = (const float*)d_in[4];
    const float* W2  = (const float*)d_in[5];
    const float* b2  = (const float*)d_in[6];
    const float* W1g = (const float*)d_in[7];
    const float* b1g = (const float*)d_in[8];
    const float* W2g = (const float*)d_in[9];
    const float* b2g = (const float*)d_in[10];
    float* out = (float*)d_out;

    kPrep<<<1216, 256>>>(H, P, G, W1, W1g, W2, W2g);
    kGemm1<<<256, 128>>>(b1, b1g);
    kGemm2<<<256, 128>>>(b2, b2g, P, G);
    finish_kernel<<<1, 1>>>(out);
}

// round 8
// speedup vs baseline: 3.0369x; 1.0713x over previous
#include <cuda_runtime.h>
#include <cuda_bf16.h>
#include <cstdint>

#define NROWS 1024
#define DIM   256
#define HID   512
#define RS2   40          // smem row stride (bf16) for BK=32 tiles: 80B, conflict-free LDSM
#define ASZ   (64 * RS2 * 2)   // 5120 B per 64x32 bf16 tile
#define BUFSZ (4 * ASZ)        // Ah, Al, Bh, Bl

// ============================ device scratch =================================
__device__ __align__(16) __nv_bfloat16 g_Xh[2][NROWS * DIM];     // H, P (hi)
__device__ __align__(16) __nv_bfloat16 g_Xl[2][NROWS * DIM];     // H, P (lo)
__device__ __align__(16) __nv_bfloat16 g_W1t_h [HID * DIM],      g_W1t_l [HID * DIM];      // [512n][256k]
__device__ __align__(16) __nv_bfloat16 g_W1gt_h[HID * 2 * DIM],  g_W1gt_l[HID * 2 * DIM];  // [512n][512k]
__device__ __align__(16) __nv_bfloat16 g_W2t_h [DIM * HID],      g_W2t_l [DIM * HID];      // [256n][512k]
__device__ __align__(16) __nv_bfloat16 g_W2gt_h[DIM * HID],      g_W2gt_l[DIM * HID];
__device__ __align__(16) __nv_bfloat16 g_A1h[2][NROWS * HID],    g_A1l[2][NROWS * HID];
__device__ __align__(16) float  g_ypart[2 * 32 * DIM];
__device__ double g_acc;
__device__ unsigned g_ticket;

// ============================ helpers ========================================
__device__ __forceinline__ uint32_t smem_u32(const void* p) {
    uint32_t a;
    asm("{ .reg .u64 t; cvta.to.shared.u64 t, %1; cvt.u32.u64 %0, t; }" : "=r"(a) : "l"(p));
    return a;
}
__device__ __forceinline__ void cvt2(float v0, float v1, uint32_t& hp, uint32_t& lp) {
    __nv_bfloat16 h0 = __float2bfloat16(v0);
    __nv_bfloat16 h1 = __float2bfloat16(v1);
    __nv_bfloat16 l0 = __float2bfloat16(v0 - __bfloat162float(h0));
    __nv_bfloat16 l1 = __float2bfloat16(v1 - __bfloat162float(h1));
    hp = ((uint32_t)__bfloat16_as_ushort(h1) << 16) | __bfloat16_as_ushort(h0);
    lp = ((uint32_t)__bfloat16_as_ushort(l1) << 16) | __bfloat16_as_ushort(l0);
}
__device__ __forceinline__ void mma16816(float* c, const uint32_t* a,
                                         const uint32_t b0, const uint32_t b1) {
    asm volatile(
        "mma.sync.aligned.m16n8k16.row.col.f32.bf16.bf16.f32 "
        "{%0,%1,%2,%3}, {%4,%5,%6,%7}, {%8,%9}, {%0,%1,%2,%3};"
        : "+f"(c[0]), "+f"(c[1]), "+f"(c[2]), "+f"(c[3])
        : "r"(a[0]), "r"(a[1]), "r"(a[2]), "r"(a[3]), "r"(b0), "r"(b1));
}
#define LDSM4(r0, r1, r2, r3, addr)                                              \
    asm volatile("ldmatrix.sync.aligned.m8n8.x4.shared.b16 {%0,%1,%2,%3}, [%4];" \
        : "=r"(r0), "=r"(r1), "=r"(r2), "=r"(r3) : "r"(addr))
#define CP16(dst, src) \
    asm volatile("cp.async.cg.shared.global [%0], [%1], 16;" :: "r"(dst), "l"(src))
#define CP_COMMIT() asm volatile("cp.async.commit_group;" ::: "memory")
#define CP_WAIT1()  asm volatile("cp.async.wait_group 1;" ::: "memory")
#define CP_WAIT0()  asm volatile("cp.async.wait_group 0;" ::: "memory")

// ============================================================================
// kPrep: split X -> bf16 hi/lo; transpose+split weights to [n][k]; means partials.
// ============================================================================
__global__ void __launch_bounds__(256) kPrep(const float* __restrict__ H,
                                             const float* __restrict__ P,
                                             const float* __restrict__ G,
                                             const float* __restrict__ W1,
                                             const float* __restrict__ W1g,
                                             const float* __restrict__ W2,
                                             const float* __restrict__ W2g)
{
    const int bid = blockIdx.x, tid = threadIdx.x;
    if (bid == 0 && tid == 0) { g_acc = 0.0; g_ticket = 0u; }

    if (bid < 512) {                       // ---- X split ----
        const int which = bid >> 8;
        const float* X = which ? P : H;
        const int base = (bid & 255) * 1024 + tid * 4;
        float4 v = *reinterpret_cast<const float4*>(&X[base]);
        uint32_t h0, l0, h1, l1;
        cvt2(v.x, v.y, h0, l0);
        cvt2(v.z, v.w, h1, l1);
        *reinterpret_cast<uint2*>(&g_Xh[which][base]) = make_uint2(h0, h1);
        *reinterpret_cast<uint2*>(&g_Xl[which][base]) = make_uint2(l0, l1);
        return;
    }

    if (bid < 1152) {                      // ---- weight transpose+split ----
        int t = bid - 512;
        const float* src; __nv_bfloat16 *dh, *dl; int K, N, kt, nt;
        if (t < 128)      { src = W1;  dh = g_W1t_h;  dl = g_W1t_l;  K = 256; N = 512; kt = t >> 4; nt = t & 15; }
        else if (t < 384) { t -= 128; src = W1g; dh = g_W1gt_h; dl = g_W1gt_l; K = 512; N = 512; kt = t >> 4; nt = t & 15; }
        else if (t < 512) { t -= 384; src = W2;  dh = g_W2t_h;  dl = g_W2t_l;  K = 512; N = 256; kt = t >> 3; nt = t & 7; }
        else              { t -= 512; src = W2g; dh = g_W2gt_h; dl = g_W2gt_l; K = 512; N = 256; kt = t >> 3; nt = t & 7; }
        const int k0 = kt * 32, n0 = nt * 32;

        __shared__ float tile[32][33];
        {
            int r = tid >> 3, c4 = tid & 7;
            float4 v = *reinterpret_cast<const float4*>(&src[(k0 + r) * N + n0 + c4 * 4]);
            tile[r][c4*4+0] = v.x; tile[r][c4*4+1] = v.y;
            tile[r][c4*4+2] = v.z; tile[r][c4*4+3] = v.w;
        }
        __syncthreads();
        {
            int nr = tid >> 3, kc = (tid & 7) * 4;
            uint32_t h0, l0, h1, l1;
            cvt2(tile[kc+0][nr], tile[kc+1][nr], h0, l0);
            cvt2(tile[kc+2][nr], tile[kc+3][nr], h1, l1);
            size_t o = (size_t)(n0 + nr) * K + k0 + kc;
            *reinterpret_cast<uint2*>(&dh[o]) = make_uint2(h0, h1);
            *reinterpret_cast<uint2*>(&dl[o]) = make_uint2(l0, l1);
        }
        return;
    }

    {                                      // ---- means partials ----
        const int t = bid - 1152;
        const int which = t >> 5, part = t & 31;
        const float* Y = which ? G : P;
        const int r0 = part * 32;
        float s = 0.f;
        #pragma unroll 8
        for (int r = 0; r < 32; ++r) s += Y[(r0 + r) * DIM + tid];
        g_ypart[(which * 32 + part) * DIM + tid] = s;
    }
}

// ============================================================================
// cp.async chunk loader: 64x32 bf16 tile pairs (A hi/lo, B hi/lo) into buffer.
// 8 x 16B per thread.
// ============================================================================
__device__ __forceinline__ void load_async32(uint32_t dst,
    const __nv_bfloat16* __restrict__ Ah, const __nv_bfloat16* __restrict__ Al,
    int m0, int lda, int ka,
    const __nv_bfloat16* __restrict__ Bh, const __nv_bfloat16* __restrict__ Bl,
    int n0, int ldb, int kb, int tid)
{
    #pragma unroll
    for (int i = 0; i < 2; ++i) {
        int idx = tid + i * 128;           // 256 granules per tile
        int row = idx >> 2, w = idx & 3;
        uint32_t doff = (uint32_t)row * (RS2 * 2) + w * 16;
        size_t sa = (size_t)(m0 + row) * lda + ka + w * 8;
        size_t sb = (size_t)(n0 + row) * ldb + kb + w * 8;
        CP16(dst + 0 * ASZ + doff, Ah + sa);
        CP16(dst + 1 * ASZ + doff, Al + sa);
        CP16(dst + 2 * ASZ + doff, Bh + sb);
        CP16(dst + 3 * ASZ + doff, Bl + sb);
    }
}

// ============================================================================
// consume one 64x64x32 chunk with ldmatrix + 3-product bf16-split HMMA.
// ============================================================================
__device__ __forceinline__ void consume32(uint32_t b, float acc[2][4][4],
                                          int wm, int wn, int lane)
{
    const int arow  = lane & 15;
    const int akoff = (lane >> 4) * 8;
    const int g     = lane >> 3;                     // 0..3
    const int brow  = ((g >> 1) & 1) * 8 + (lane & 7);
    const int bkoff = (g & 1) * 8;
    #pragma unroll
    for (int ks = 0; ks < 2; ++ks) {
        const int kb = ks * 16;
        uint32_t ah[2][4], al[2][4];
        #pragma unroll
        for (int mi = 0; mi < 2; ++mi) {
            uint32_t ro = (uint32_t)(wm * 32 + mi * 16 + arow) * (RS2 * 2) + (kb + akoff) * 2;
            LDSM4(ah[mi][0], ah[mi][1], ah[mi][2], ah[mi][3], b + 0 * ASZ + ro);
            LDSM4(al[mi][0], al[mi][1], al[mi][2], al[mi][3], b + 1 * ASZ + ro);
        }
        uint32_t bh[2][4], bl[2][4];                 // [njp][r]: r0/r1 = nj even, r2/r3 = nj odd
        #pragma unroll
        for (int njp = 0; njp < 2; ++njp) {
            uint32_t ro = (uint32_t)(wn * 32 + njp * 16 + brow) * (RS2 * 2) + (kb + bkoff) * 2;
            LDSM4(bh[njp][0], bh[njp][1], bh[njp][2], bh[njp][3], b + 2 * ASZ + ro);
            LDSM4(bl[njp][0], bl[njp][1], bl[njp][2], bl[njp][3], b + 3 * ASZ + ro);
        }
        #pragma unroll
        for (int mi = 0; mi < 2; ++mi)
            #pragma unroll
            for (int njp = 0; njp < 2; ++njp) {
                mma16816(acc[mi][2*njp],     ah[mi], bh[njp][0], bh[njp][1]);
                mma16816(acc[mi][2*njp],     ah[mi], bl[njp][0], bl[njp][1]);
                mma16816(acc[mi][2*njp],     al[mi], bh[njp][0], bh[njp][1]);
                mma16816(acc[mi][2*njp + 1], ah[mi], bh[njp][2], bh[njp][3]);
                mma16816(acc[mi][2*njp + 1], ah[mi], bl[njp][2], bl[njp][3]);
                mma16816(acc[mi][2*njp + 1], al[mi], bh[njp][2], bh[njp][3]);
            }
    }
}

// ============================================================================
// kGemm1: layer-1 (relu, re-split hi/lo). 256 CTAs: prob(2) x m(16) x n(8).
// ============================================================================
__global__ void __launch_bounds__(128) kGemm1(const float* __restrict__ b1,
                                              const float* __restrict__ b1g)
{
    __shared__ __align__(16) char bufs[2 * BUFSZ];
    const uint32_t sb = smem_u32(bufs);
    const int tid  = threadIdx.x;
    const int lane = tid & 31, wrp = tid >> 5;
    const int wm   = wrp >> 1, wn = wrp & 1;
    const int bid  = blockIdx.x;
    const int prob = bid >> 7, t = bid & 127;
    const int m0   = (t >> 3) * 64, n0 = (t & 7) * 64;

    const __nv_bfloat16* Wh = prob ? g_W1gt_h : g_W1t_h;
    const __nv_bfloat16* Wl = prob ? g_W1gt_l : g_W1t_l;
    const int K = prob ? 2 * DIM : DIM;
    const int nch = K / 32;

    float acc[2][4][4] = {};
    load_async32(sb, g_Xh[0], g_Xl[0], m0, DIM, 0, Wh, Wl, n0, K, 0, tid);
    CP_COMMIT();
    for (int ch = 0; ch < nch; ++ch) {
        if (ch + 1 < nch) {
            int k0 = (ch + 1) * 32;
            int xi = (prob && k0 >= DIM) ? 1 : 0;    // concat: H then P
            load_async32(sb + ((ch + 1) & 1) * BUFSZ,
                         g_Xh[xi], g_Xl[xi], m0, DIM, k0 & (DIM - 1),
                         Wh, Wl, n0, K, k0, tid);
            CP_COMMIT();
            CP_WAIT1();
        } else {
            CP_WAIT0();
        }
        __syncthreads();
        consume32(sb + (ch & 1) * BUFSZ, acc, wm, wn, lane);
        __syncthreads();
    }

    const float* Bias = prob ? b1g : b1;
    __nv_bfloat16* Oh = g_A1h[prob];
    __nv_bfloat16* Ol = g_A1l[prob];
    const int qr = lane >> 2, qc = (lane & 3) * 2;
    #pragma unroll
    for (int mi = 0; mi < 2; ++mi) {
        #pragma unroll
        for (int nj = 0; nj < 4; ++nj) {
            int row = m0 + wm * 32 + mi * 16 + qr;
            int col = n0 + wn * 32 + nj * 8 + qc;
            float bz0 = Bias[col], bz1 = Bias[col + 1];
            uint32_t hp, lp;
            cvt2(fmaxf(acc[mi][nj][0] + bz0, 0.f), fmaxf(acc[mi][nj][1] + bz1, 0.f), hp, lp);
            *reinterpret_cast<uint32_t*>(&Oh[(size_t)row * HID + col]) = hp;
            *reinterpret_cast<uint32_t*>(&Ol[(size_t)row * HID + col]) = lp;
            cvt2(fmaxf(acc[mi][nj][2] + bz0, 0.f), fmaxf(acc[mi][nj][3] + bz1, 0.f), hp, lp);
            *reinterpret_cast<uint32_t*>(&Oh[(size_t)(row + 8) * HID + col]) = hp;
            *reinterpret_cast<uint32_t*>(&Ol[(size_t)(row + 8) * HID + col]) = lp;
        }
    }
}

// ============================================================================
// kGemm2: layer-2, split-K x2, fused CLUB epilogue, ticket-fused finish.
// 256 CTAs: prob(2) x m(16) x n(4) x chunk(2).
// ============================================================================
__global__ void __launch_bounds__(128) kGemm2(const float* __restrict__ b2,
                                              const float* __restrict__ b2g,
                                              const float* __restrict__ P,
                                              const float* __restrict__ G,
                                              float* __restrict__ out)
{
    __shared__ __align__(16) char bufs[2 * BUFSZ];
    __shared__ float  ym_s[64];
    __shared__ double red[4];
    const uint32_t sb = smem_u32(bufs);
    const int tid  = threadIdx.x;
    const int lane = tid & 31, wrp = tid >> 5;
    const int wm   = wrp >> 1, wn = wrp & 1;
    const int bid  = blockIdx.x;
    const int prob  = bid >> 7, t = bid & 127;
    const int m0    = (t >> 3) * 64;
    const int n0    = ((t >> 1) & 3) * 64;
    const int chunk = t & 1;
    const int kbeg  = chunk * 256;

    if (tid < 64) {                        // ym for this n-tile
        float sm = 0.f;
        #pragma unroll 8
        for (int b = 0; b < 32; ++b) sm += g_ypart[(prob * 32 + b) * DIM + n0 + tid];
        ym_s[tid] = sm * (1.0f / NROWS);
    }

    const __nv_bfloat16* Ah = g_A1h[prob];
    const __nv_bfloat16* Al = g_A1l[prob];
    const __nv_bfloat16* Wh = prob ? g_W2gt_h : g_W2t_h;
    const __nv_bfloat16* Wl = prob ? g_W2gt_l : g_W2t_l;

    float acc[2][4][4] = {};
    load_async32(sb, Ah, Al, m0, HID, kbeg, Wh, Wl, n0, HID, kbeg, tid);
    CP_COMMIT();
    for (int ch = 0; ch < 8; ++ch) {
        if (ch < 7) {
            int k0 = kbeg + (ch + 1) * 32;
            load_async32(sb + ((ch + 1) & 1) * BUFSZ,
                         Ah, Al, m0, HID, k0, Wh, Wl, n0, HID, k0, tid);
            CP_COMMIT();
            CP_WAIT1();
        } else {
            CP_WAIT0();
        }
        __syncthreads();
        consume32(sb + (ch & 1) * BUFSZ, acc, wm, wn, lane);
        __syncthreads();
    }

    const float* Bias = prob ? b2g : b2;
    const float* Y    = prob ? G   : P;
    const bool  wb    = (chunk == 0);      // bias rides on chunk 0 (linearity)
    const int qr = lane >> 2, qc = (lane & 3) * 2;
    float local = 0.f;
    #pragma unroll
    for (int mi = 0; mi < 2; ++mi) {
        #pragma unroll
        for (int nj = 0; nj < 4; ++nj) {
            int row = m0 + wm * 32 + mi * 16 + qr;
            int col = n0 + wn * 32 + nj * 8 + qc;
            float bz0 = wb ? Bias[col]     : 0.f;
            float bz1 = wb ? Bias[col + 1] : 0.f;
            float ym0 = ym_s[col - n0], ym1 = ym_s[col - n0 + 1];
            float2 y0 = *reinterpret_cast<const float2*>(&Y[(size_t)row * DIM + col]);
            float2 y1 = *reinterpret_cast<const float2*>(&Y[(size_t)(row + 8) * DIM + col]);
            local += (acc[mi][nj][0] + bz0) * (y0.x - ym0)
                   + (acc[mi][nj][1] + bz1) * (y0.y - ym1)
                   + (acc[mi][nj][2] + bz0) * (y1.x - ym0)
                   + (acc[mi][nj][3] + bz1) * (y1.y - ym1);
        }
    }
    #pragma unroll
    for (int off = 16; off > 0; off >>= 1)
        local += __shfl_xor_sync(0xFFFFFFFF, local, off);
    if (lane == 0) red[wrp] = (double)local;
    __syncthreads();
    if (tid == 0) {
        atomicAdd(&g_acc, (red[0] + red[1]) + (red[2] + red[3]));
        __threadfence();
        unsigned tk = atomicAdd(&g_ticket, 1u);
        if (tk == (unsigned)(gridDim.x - 1)) {       // last block: finish
            double total = atomicAdd(&g_acc, 0.0);   // atomic read (L2-coherent)
            out[0] = (float)(total * (1.0 / NROWS));
        }
    }
}

// ----------------------------------------------------------------------------
extern "C" void kernel_launch(void* const* d_in, const int* in_sizes, int n_in,
                              void* d_out, int out_size)
{
    const float* H   = (const float*)d_in[0];
    const float* P   = (const float*)d_in[1];
    const float* G   = (const float*)d_in[2];
    const float* W1  = (const float*)d_in[3];
    const float* b1  = (const float*)d_in[4];
    const float* W2  = (const float*)d_in[5];
    const float* b2  = (const float*)d_in[6];
    const float* W1g = (const float*)d_in[7];
    const float* b1g = (const float*)d_in[8];
    const float* W2g = (const float*)d_in[9];
    const float* b2g = (const float*)d_in[10];
    float* out = (float*)d_out;

    kPrep<<<1216, 256>>>(H, P, G, W1, W1g, W2, W2g);
    kGemm1<<<256, 128>>>(b1, b1g);
    kGemm2<<<256, 128>>>(b2, b2g, P, G, out);
}